// round 5
// baseline (speedup 1.0000x reference)
#include <cuda_runtime.h>
#include <math.h>
#include <stdint.h>

#define N_NODES 50000
#define N_EDGES 800000
#define D 128
#define DE 16
#define NACT 32
#define NEG_SLOPE 0.2f
#define EPS_ 1e-16f
#define TINYF 1.17549435e-38f

// ---------------- scratch (static device globals; no allocation) ----------------
__device__ float g_h1[N_NODES * D];       // layer-1 node features
__device__ float g_lat[N_NODES * D];      // latent (layer-1 output)
__device__ float g_h2[N_NODES];           // layer-2 node features (scalar)
__device__ float g_h3[N_NODES * NACT];    // layer-3 node features (32)
__device__ float g_sc1[N_EDGES];          // layer-1 scores, CSR order
__device__ float g_sc2[N_EDGES];          // layer-2 scores, CSR order
__device__ int   g_cnt[N_NODES];
__device__ int   g_off[N_NODES + 1];
__device__ int   g_cur[N_NODES];
__device__ int   g_csr[N_EDGES];          // edge id by CSR position
__device__ int   g_csrc[N_EDGES];         // src node by CSR position
__device__ int   g_pos[N_EDGES];          // edge id -> CSR position
__device__ float g_logits[N_NODES];       // node logits (layer 2 out)
__device__ unsigned long long g_amax;     // argmax (orderable z << 32 | ~idx)
__device__ unsigned int g_mlog;           // orderable max logit
__device__ float g_sexp;                  // sum exp(logit - max)

// ---------------- threefry2x32 (JAX-compatible) ----------------
#define TFR(x0, x1, r) { x0 += x1; x1 = ((x1 << r) | (x1 >> (32 - r))); x1 ^= x0; }

__device__ __forceinline__ void threefry(uint32_t k0, uint32_t k1, uint32_t x0, uint32_t x1,
                                         uint32_t& o0, uint32_t& o1) {
    uint32_t k2 = k0 ^ k1 ^ 0x1BD11BDAu;
    x0 += k0; x1 += k1;
    TFR(x0, x1, 13) TFR(x0, x1, 15) TFR(x0, x1, 26) TFR(x0, x1, 6)  x0 += k1; x1 += k2 + 1u;
    TFR(x0, x1, 17) TFR(x0, x1, 29) TFR(x0, x1, 16) TFR(x0, x1, 24) x0 += k2; x1 += k0 + 2u;
    TFR(x0, x1, 13) TFR(x0, x1, 15) TFR(x0, x1, 26) TFR(x0, x1, 6)  x0 += k0; x1 += k1 + 3u;
    TFR(x0, x1, 17) TFR(x0, x1, 29) TFR(x0, x1, 16) TFR(x0, x1, 24) x0 += k1; x1 += k2 + 4u;
    TFR(x0, x1, 13) TFR(x0, x1, 15) TFR(x0, x1, 26) TFR(x0, x1, 6)  x0 += k2; x1 += k0 + 5u;
    o0 = x0; o1 = x1;
}

// JAX partitionable 32-bit random bits: (bits1 ^ bits2) of threefry(key, (hi=0, lo=i))
__device__ __forceinline__ uint32_t jax_bits32(uint32_t k0, uint32_t k1, uint32_t i) {
    uint32_t o0, o1;
    threefry(k0, k1, 0u, i, o0, o1);
    return o0 ^ o1;
}

__device__ __forceinline__ float gumbel_from_bits(uint32_t bits) {
    float u = __uint_as_float((bits >> 9) | 0x3f800000u) - 1.0f;
    u = fmaxf(u, TINYF);
    return -logf(-logf(u));
}

// monotone orderable float <-> uint
__device__ __forceinline__ uint32_t fford(float f) {
    uint32_t b = __float_as_uint(f);
    return (b & 0x80000000u) ? ~b : (b | 0x80000000u);
}
__device__ __forceinline__ float funord(uint32_t u) {
    uint32_t b = (u & 0x80000000u) ? (u ^ 0x80000000u) : ~u;
    return __uint_as_float(b);
}

__device__ __forceinline__ float lrelu(float x) { return x > 0.f ? x : NEG_SLOPE * x; }

// ---------------- kernels ----------------
__global__ void k_init() {
    int i = blockIdx.x * blockDim.x + threadIdx.x;
    if (i < N_NODES) g_cnt[i] = 0;
    if (i == 0) { g_amax = 0ull; g_mlog = 0u; g_sexp = 0.f; }
}

// h1 = x @ Wl1 + bl1 : warp handles 4 rows, lane handles 4 cols
__global__ void k_h1(const float* __restrict__ x, const float* __restrict__ W,
                     const float* __restrict__ b) {
    int w = (blockIdx.x * blockDim.x + threadIdx.x) >> 5;
    int lane = threadIdx.x & 31;
    int r0 = w * 4;
    if (r0 >= N_NODES) return;
    int c = lane * 4;
    float a0x=0,a0y=0,a0z=0,a0w=0, a1x=0,a1y=0,a1z=0,a1w=0;
    float a2x=0,a2y=0,a2z=0,a2w=0, a3x=0,a3y=0,a3z=0,a3w=0;
    for (int k = 0; k < D; k++) {
        float4 wv = *(const float4*)&W[k * D + c];
        float x0 = __ldg(&x[(size_t)(r0 + 0) * D + k]);
        float x1 = __ldg(&x[(size_t)(r0 + 1) * D + k]);
        float x2 = __ldg(&x[(size_t)(r0 + 2) * D + k]);
        float x3 = __ldg(&x[(size_t)(r0 + 3) * D + k]);
        a0x += x0*wv.x; a0y += x0*wv.y; a0z += x0*wv.z; a0w += x0*wv.w;
        a1x += x1*wv.x; a1y += x1*wv.y; a1z += x1*wv.z; a1w += x1*wv.w;
        a2x += x2*wv.x; a2y += x2*wv.y; a2z += x2*wv.z; a2w += x2*wv.w;
        a3x += x3*wv.x; a3y += x3*wv.y; a3z += x3*wv.z; a3w += x3*wv.w;
    }
    float4 bv = *(const float4*)&b[c];
    float4 o;
    o.x=a0x+bv.x; o.y=a0y+bv.y; o.z=a0z+bv.z; o.w=a0w+bv.w; *(float4*)&g_h1[(size_t)(r0+0)*D+c]=o;
    o.x=a1x+bv.x; o.y=a1y+bv.y; o.z=a1z+bv.z; o.w=a1w+bv.w; *(float4*)&g_h1[(size_t)(r0+1)*D+c]=o;
    o.x=a2x+bv.x; o.y=a2y+bv.y; o.z=a2z+bv.z; o.w=a2w+bv.w; *(float4*)&g_h1[(size_t)(r0+2)*D+c]=o;
    o.x=a3x+bv.x; o.y=a3y+bv.y; o.z=a3z+bv.z; o.w=a3w+bv.w; *(float4*)&g_h1[(size_t)(r0+3)*D+c]=o;
}

__global__ void k_count(const int* __restrict__ dst) {
    int e = blockIdx.x * blockDim.x + threadIdx.x;
    if (e < N_EDGES) atomicAdd(&g_cnt[dst[e]], 1);
}

// single-block exclusive scan of g_cnt -> g_off (and g_cur copy)
__global__ void k_scan() {
    __shared__ int warp_sums[32];
    __shared__ int s_carry;
    int t = threadIdx.x, lane = t & 31, wid = t >> 5;
    if (t == 0) s_carry = 0;
    __syncthreads();
    for (int base = 0; base < N_NODES; base += 1024) {
        int i = base + t;
        int v = (i < N_NODES) ? g_cnt[i] : 0;
        int inc = v;
        for (int d2 = 1; d2 < 32; d2 <<= 1) {
            int y = __shfl_up_sync(0xffffffffu, inc, d2);
            if (lane >= d2) inc += y;
        }
        if (lane == 31) warp_sums[wid] = inc;
        __syncthreads();
        if (wid == 0) {
            int ws = warp_sums[lane];
            for (int d2 = 1; d2 < 32; d2 <<= 1) {
                int y = __shfl_up_sync(0xffffffffu, ws, d2);
                if (lane >= d2) ws += y;
            }
            warp_sums[lane] = ws;
        }
        __syncthreads();
        int excl = inc - v + (wid > 0 ? warp_sums[wid - 1] : 0) + s_carry;
        if (i < N_NODES) { g_off[i] = excl; g_cur[i] = excl; }
        __syncthreads();
        if (t == 1023) s_carry = excl + v;
        __syncthreads();
    }
    if (t == 0) g_off[N_NODES] = s_carry;
}

__global__ void k_scatter(const int* __restrict__ src, const int* __restrict__ dst) {
    int e = blockIdx.x * blockDim.x + threadIdx.x;
    if (e >= N_EDGES) return;
    int d = dst[e];
    int s = atomicAdd(&g_cur[d], 1);
    g_csr[s] = e;
    g_csrc[s] = src[e];
    g_pos[e] = s;
}

// layer-1 edge scores: warp per edge (grid-stride); We1 (16x128) held in regs per warp
__global__ void __launch_bounds__(256) k_score1(const int* __restrict__ src, const int* __restrict__ dst,
                                                const float* __restrict__ ea, const float* __restrict__ We,
                                                const float* __restrict__ att) {
    int lane = threadIdx.x & 31;
    int warp = (blockIdx.x * blockDim.x + threadIdx.x) >> 5;
    int nwarp = (gridDim.x * blockDim.x) >> 5;
    int c = lane * 4;
    float4 wreg[DE];
#pragma unroll
    for (int k = 0; k < DE; k++) wreg[k] = *(const float4*)&We[k * D + c];
    float4 av = *(const float4*)&att[c];
    for (int e = warp; e < N_EDGES; e += nwarp) {
        int j = src[e], i = dst[e];
        float4 hi4 = *(const float4*)&g_h1[(size_t)i * D + c];
        float4 hj4 = *(const float4*)&g_h1[(size_t)j * D + c];
        float tx = hi4.x + hj4.x, ty = hi4.y + hj4.y, tz = hi4.z + hj4.z, tw = hi4.w + hj4.w;
        const float4* ea4 = (const float4*)&ea[(size_t)e * DE];
#pragma unroll
        for (int q = 0; q < 4; q++) {
            float4 v = __ldg(&ea4[q]);
            float4 w0 = wreg[q*4+0], w1 = wreg[q*4+1], w2 = wreg[q*4+2], w3 = wreg[q*4+3];
            tx += v.x*w0.x + v.y*w1.x + v.z*w2.x + v.w*w3.x;
            ty += v.x*w0.y + v.y*w1.y + v.z*w2.y + v.w*w3.y;
            tz += v.x*w0.z + v.y*w1.z + v.z*w2.z + v.w*w3.z;
            tw += v.x*w0.w + v.y*w1.w + v.z*w2.w + v.w*w3.w;
        }
        float s = lrelu(tx)*av.x + lrelu(ty)*av.y + lrelu(tz)*av.z + lrelu(tw)*av.w;
        for (int d2 = 16; d2; d2 >>= 1) s += __shfl_xor_sync(0xffffffffu, s, d2);
        if (lane == 0) g_sc1[g_pos[e]] = s;
    }
}

// layer-1 segment softmax + aggregation: warp per dst row
__global__ void k_agg1(const float* __restrict__ bias) {
    int gw = (blockIdx.x * blockDim.x + threadIdx.x) >> 5;
    if (gw >= N_NODES) return;
    int lane = threadIdx.x & 31, c = lane * 4;
    int beg = g_off[gw], end = g_off[gw + 1];
    float m = -INFINITY;
    for (int p = beg + lane; p < end; p += 32) m = fmaxf(m, g_sc1[p]);
    for (int d2 = 16; d2; d2 >>= 1) m = fmaxf(m, __shfl_xor_sync(0xffffffffu, m, d2));
    float ax = 0, ay = 0, az = 0, aw = 0, den = 0;
    for (int p = beg; p < end; p++) {
        float ex = expf(g_sc1[p] - m);
        int j = g_csrc[p];
        float4 hv = *(const float4*)&g_h1[(size_t)j * D + c];
        den += ex; ax += ex * hv.x; ay += ex * hv.y; az += ex * hv.z; aw += ex * hv.w;
    }
    float inv = 1.f / (den + EPS_);
    float4 bv = *(const float4*)&bias[c];
    float4 o = { ax * inv + bv.x, ay * inv + bv.y, az * inv + bv.z, aw * inv + bv.w };
    *(float4*)&g_lat[(size_t)gw * D + c] = o;
}

// h2 = lat@Wl2 + bl2 ; h3 = lat@Wl3 + bl3 : warp per row
__global__ void k_h23(const float* __restrict__ Wl2, const float* __restrict__ bl2,
                      const float* __restrict__ Wl3, const float* __restrict__ bl3) {
    int gw = (blockIdx.x * blockDim.x + threadIdx.x) >> 5;
    if (gw >= N_NODES) return;
    int lane = threadIdx.x & 31;
    float4 r = *(const float4*)&g_lat[(size_t)gw * D + lane * 4];
    // h2
    float4 w2 = *(const float4*)&Wl2[lane * 4];
    float p = r.x * w2.x + r.y * w2.y + r.z * w2.z + r.w * w2.w;
    for (int d2 = 16; d2; d2 >>= 1) p += __shfl_xor_sync(0xffffffffu, p, d2);
    if (lane == 0) g_h2[gw] = p + bl2[0];
    // h3 (lane = output col)
    float acc = 0.f;
#pragma unroll
    for (int comp = 0; comp < 4; comp++) {
        float v = (comp == 0) ? r.x : (comp == 1) ? r.y : (comp == 2) ? r.z : r.w;
#pragma unroll
        for (int s = 0; s < 32; s++) {
            float lk = __shfl_sync(0xffffffffu, v, s);
            acc += lk * __ldg(&Wl3[(s * 4 + comp) * NACT + lane]);
        }
    }
    g_h3[(size_t)gw * NACT + lane] = acc + bl3[lane];
}

// layer-2 edge scores: thread per edge (scalar)
__global__ void k_score2(const int* __restrict__ src, const int* __restrict__ dst,
                         const float* __restrict__ ea, const float* __restrict__ We2,
                         const float* __restrict__ att2) {
    int e = blockIdx.x * blockDim.x + threadIdx.x;
    if (e >= N_EDGES) return;
    float t = g_h2[dst[e]] + g_h2[src[e]];
    const float4* ea4 = (const float4*)&ea[(size_t)e * DE];
#pragma unroll
    for (int q = 0; q < 4; q++) {
        float4 v = __ldg(&ea4[q]);
        t += v.x * We2[q*4+0] + v.y * We2[q*4+1] + v.z * We2[q*4+2] + v.w * We2[q*4+3];
    }
    t = lrelu(t);
    g_sc2[g_pos[e]] = t * att2[0];
}

// layer-2 segment softmax + aggregation -> node logits: warp per row
__global__ void k_agg2(const float* __restrict__ bias2) {
    int gw = (blockIdx.x * blockDim.x + threadIdx.x) >> 5;
    if (gw >= N_NODES) return;
    int lane = threadIdx.x & 31;
    int beg = g_off[gw], end = g_off[gw + 1];
    float m = -INFINITY;
    for (int p = beg + lane; p < end; p += 32) m = fmaxf(m, g_sc2[p]);
    for (int d2 = 16; d2; d2 >>= 1) m = fmaxf(m, __shfl_xor_sync(0xffffffffu, m, d2));
    float num = 0, den = 0;
    for (int p = beg + lane; p < end; p += 32) {
        float ex = expf(g_sc2[p] - m);
        den += ex;
        num += ex * g_h2[g_csrc[p]];
    }
    for (int d2 = 16; d2; d2 >>= 1) {
        num += __shfl_xor_sync(0xffffffffu, num, d2);
        den += __shfl_xor_sync(0xffffffffu, den, d2);
    }
    if (lane == 0) g_logits[gw] = num / (den + EPS_) + bias2[0];
}

// node selection pass A: gumbel + argmax(z), max logit
__global__ void k_sel() {
    int i = blockIdx.x * blockDim.x + threadIdx.x;
    unsigned long long key = 0ull;
    unsigned int lk = 0u;
    if (i < N_NODES) {
        float lg = g_logits[i];
        uint32_t k1a, k1b; threefry(0u, 42u, 0u, 0u, k1a, k1b);     // foldlike split: child 0
        uint32_t bits = jax_bits32(k1a, k1b, (uint32_t)i);          // partitionable: o0 ^ o1
        float z = lg + gumbel_from_bits(bits);
        key = (((unsigned long long)fford(z)) << 32) | (unsigned long long)(0xFFFFFFFFu - (unsigned)i);
        lk = fford(lg);
    }
    for (int d2 = 16; d2; d2 >>= 1) {
        unsigned long long ok = __shfl_xor_sync(0xffffffffu, key, d2); if (ok > key) key = ok;
        unsigned int ol = __shfl_xor_sync(0xffffffffu, lk, d2); if (ol > lk) lk = ol;
    }
    __shared__ unsigned long long sk[8];
    __shared__ unsigned int sl[8];
    int lane = threadIdx.x & 31, w = threadIdx.x >> 5;
    if (lane == 0) { sk[w] = key; sl[w] = lk; }
    __syncthreads();
    if (threadIdx.x == 0) {
        for (int q = 1; q < 8; q++) { if (sk[q] > key) key = sk[q]; if (sl[q] > lk) lk = sl[q]; }
        atomicMax(&g_amax, key);
        atomicMax(&g_mlog, lk);
    }
}

// node selection pass B: sum exp(logit - max)
__global__ void k_sumexp() {
    int i = blockIdx.x * blockDim.x + threadIdx.x;
    float ml = funord(g_mlog);
    float v = (i < N_NODES) ? expf(g_logits[i] - ml) : 0.f;
    for (int d2 = 16; d2; d2 >>= 1) v += __shfl_xor_sync(0xffffffffu, v, d2);
    __shared__ float sv[8];
    int lane = threadIdx.x & 31, w = threadIdx.x >> 5;
    if (lane == 0) sv[w] = v;
    __syncthreads();
    if (threadIdx.x == 0) {
        float t = 0;
        for (int q = 0; q < 8; q++) t += sv[q];
        atomicAdd(&g_sexp, t);
    }
}

// final: layer-3 GATv2 only at selected node + action sampling + output
__global__ void k_final(const float* __restrict__ ea, const float* __restrict__ We3,
                        const float* __restrict__ att3, const float* __restrict__ bias3,
                        float* __restrict__ out) {
    __shared__ float s3[4096];
    __shared__ int ssrc[4096];
    int t = threadIdx.x, lane = t & 31, w = t >> 5;
    int sel = (int)(0xFFFFFFFFu - (uint32_t)(g_amax & 0xFFFFFFFFull));
    int beg = g_off[sel], end = g_off[sel + 1];
    int cnt = end - beg;
    if (cnt > 4096) cnt = 4096;
    // scores: warp per edge, lane = dim
    for (int p = w; p < cnt; p += 8) {
        int eid = g_csr[beg + p];
        int j = g_csrc[beg + p];
        float tt = g_h3[(size_t)sel * NACT + lane] + g_h3[(size_t)j * NACT + lane];
#pragma unroll
        for (int k = 0; k < DE; k++) tt += ea[(size_t)eid * DE + k] * We3[k * NACT + lane];
        tt = lrelu(tt);
        float s = tt * att3[lane];
        for (int d2 = 16; d2; d2 >>= 1) s += __shfl_xor_sync(0xffffffffu, s, d2);
        if (lane == 0) { s3[p] = s; ssrc[p] = j; }
    }
    __syncthreads();
    if (w == 0) {
        float m = -INFINITY;
        for (int p = lane; p < cnt; p += 32) m = fmaxf(m, s3[p]);
        for (int d2 = 16; d2; d2 >>= 1) m = fmaxf(m, __shfl_xor_sync(0xffffffffu, m, d2));
        float den = 0;
        for (int p = lane; p < cnt; p += 32) den += expf(s3[p] - m);
        for (int d2 = 16; d2; d2 >>= 1) den += __shfl_xor_sync(0xffffffffu, den, d2);
        float acc = 0;
        for (int p = 0; p < cnt; p++) {
            float ex = expf(s3[p] - m);
            acc += ex * g_h3[(size_t)ssrc[p] * NACT + lane];
        }
        float logit = acc / (den + EPS_) + bias3[lane];
        // gumbel with k2 (foldlike split child 1), partitionable bits = o0 ^ o1
        uint32_t k2a, k2b; threefry(0u, 42u, 0u, 1u, k2a, k2b);
        uint32_t bits = jax_bits32(k2a, k2b, (uint32_t)lane);
        float z = logit + gumbel_from_bits(bits);
        float zb = z; int ib = lane;
        for (int d2 = 16; d2; d2 >>= 1) {
            float zo = __shfl_xor_sync(0xffffffffu, zb, d2);
            int io = __shfl_xor_sync(0xffffffffu, ib, d2);
            if (zo > zb || (zo == zb && io < ib)) { zb = zo; ib = io; }
        }
        int asel = ib;
        float lm = logit;
        for (int d2 = 16; d2; d2 >>= 1) lm = fmaxf(lm, __shfl_xor_sync(0xffffffffu, lm, d2));
        float se = expf(logit - lm);
        for (int d2 = 16; d2; d2 >>= 1) se += __shfl_xor_sync(0xffffffffu, se, d2);
        float logit_sel = __shfl_sync(0xffffffffu, logit, asel);
        if (lane == 0) {
            float alp = logit_sel - lm - logf(se);
            float ml = funord(g_mlog);
            float nlp = g_logits[sel] - ml - logf(g_sexp);
            out[0] = (float)sel;
            out[1] = (float)asel;
            out[2] = nlp + alp;
        }
    }
}

// ---------------- launch ----------------
extern "C" void kernel_launch(void* const* d_in, const int* in_sizes, int n_in,
                              void* d_out, int out_size) {
    const float* x     = (const float*)d_in[0];
    const int*   ei    = (const int*)  d_in[1];
    const float* ea    = (const float*)d_in[2];
    const float* Wl1   = (const float*)d_in[3];
    const float* bl1   = (const float*)d_in[4];
    const float* We1   = (const float*)d_in[5];
    const float* att1  = (const float*)d_in[6];
    const float* bias1 = (const float*)d_in[7];
    const float* Wl2   = (const float*)d_in[8];
    const float* bl2   = (const float*)d_in[9];
    const float* We2   = (const float*)d_in[10];
    const float* att2  = (const float*)d_in[11];
    const float* bias2 = (const float*)d_in[12];
    const float* Wl3   = (const float*)d_in[13];
    const float* bl3   = (const float*)d_in[14];
    const float* We3   = (const float*)d_in[15];
    const float* att3  = (const float*)d_in[16];
    const float* bias3 = (const float*)d_in[17];
    const int* src = ei;
    const int* dst = ei + N_EDGES;
    float* out = (float*)d_out;

    int ebl = (N_EDGES + 255) / 256;
    int nbl = (N_NODES + 255) / 256;
    int wnode_bl = (N_NODES * 32 + 255) / 256;          // warp per node
    int h1_bl = ((N_NODES / 4) * 32 + 255) / 256;       // warp per 4 rows

    k_init<<<nbl, 256>>>();
    k_h1<<<h1_bl, 256>>>(x, Wl1, bl1);
    k_count<<<ebl, 256>>>(dst);
    k_scan<<<1, 1024>>>();
    k_scatter<<<ebl, 256>>>(src, dst);
    k_score1<<<592, 256>>>(src, dst, ea, We1, att1);
    k_agg1<<<wnode_bl, 256>>>(bias1);
    k_h23<<<wnode_bl, 256>>>(Wl2, bl2, Wl3, bl3);
    k_score2<<<ebl, 256>>>(src, dst, ea, We2, att2);
    k_agg2<<<wnode_bl, 256>>>(bias2);
    k_sel<<<nbl, 256>>>();
    k_sumexp<<<nbl, 256>>>();
    k_final<<<1, 256>>>(ea, We3, att3, bias3, out);
}

// round 6
// speedup vs baseline: 1.2110x; 1.2110x over previous
#include <cuda_runtime.h>
#include <math.h>
#include <stdint.h>

#define N_NODES 50000
#define N_EDGES 800000
#define D 128
#define DE 16
#define NACT 32
#define NEG_SLOPE 0.2f
#define EPS_ 1e-16f
#define TINYF 1.17549435e-38f
#define NB_SCAN 49   // ceil(50000/1024)

// ---------------- scratch ----------------
__device__ float g_h1[N_NODES * D];
__device__ float g_lat[N_NODES * D];
__device__ float g_h2[N_NODES];
__device__ float g_h3[N_NODES * NACT];
__device__ float g_sc1[N_EDGES];          // layer-1 scores, CSR order
__device__ float g_e2[N_EDGES];           // ea@We2 scalar, CSR order
__device__ int   g_cnt[N_NODES];
__device__ int   g_off[N_NODES + 1];
__device__ int   g_cur[N_NODES];
__device__ int   g_csr[N_EDGES];          // edge id by CSR position
__device__ int   g_csrc[N_EDGES];         // src node by CSR position
__device__ int   g_bsum[NB_SCAN];
__device__ float g_logits[N_NODES];
__device__ unsigned long long g_amax;
__device__ unsigned int g_mlog;
__device__ float g_sexp;

// ---------------- f32x2 packed math ----------------
typedef unsigned long long ull;
__device__ __forceinline__ ull pk2(float a, float b) {
    ull r; asm("mov.b64 %0, {%1, %2};" : "=l"(r) : "f"(a), "f"(b)); return r;
}
__device__ __forceinline__ void upk2(ull v, float& a, float& b) {
    asm("mov.b64 {%0, %1}, %2;" : "=f"(a), "=f"(b) : "l"(v));
}
__device__ __forceinline__ void ffma2(ull& d, ull a, ull b) {
    asm("fma.rn.f32x2 %0, %1, %2, %0;" : "+l"(d) : "l"(a), "l"(b));
}

// ---------------- threefry2x32 (JAX-compatible) ----------------
#define TFR(x0, x1, r) { x0 += x1; x1 = ((x1 << r) | (x1 >> (32 - r))); x1 ^= x0; }
__device__ __forceinline__ void threefry(uint32_t k0, uint32_t k1, uint32_t x0, uint32_t x1,
                                         uint32_t& o0, uint32_t& o1) {
    uint32_t k2 = k0 ^ k1 ^ 0x1BD11BDAu;
    x0 += k0; x1 += k1;
    TFR(x0, x1, 13) TFR(x0, x1, 15) TFR(x0, x1, 26) TFR(x0, x1, 6)  x0 += k1; x1 += k2 + 1u;
    TFR(x0, x1, 17) TFR(x0, x1, 29) TFR(x0, x1, 16) TFR(x0, x1, 24) x0 += k2; x1 += k0 + 2u;
    TFR(x0, x1, 13) TFR(x0, x1, 15) TFR(x0, x1, 26) TFR(x0, x1, 6)  x0 += k0; x1 += k1 + 3u;
    TFR(x0, x1, 17) TFR(x0, x1, 29) TFR(x0, x1, 16) TFR(x0, x1, 24) x0 += k1; x1 += k2 + 4u;
    TFR(x0, x1, 13) TFR(x0, x1, 15) TFR(x0, x1, 26) TFR(x0, x1, 6)  x0 += k2; x1 += k0 + 5u;
    o0 = x0; o1 = x1;
}
__device__ __forceinline__ uint32_t jax_bits32(uint32_t k0, uint32_t k1, uint32_t i) {
    uint32_t o0, o1; threefry(k0, k1, 0u, i, o0, o1); return o0 ^ o1;
}
__device__ __forceinline__ float gumbel_from_bits(uint32_t bits) {
    float u = __uint_as_float((bits >> 9) | 0x3f800000u) - 1.0f;
    u = fmaxf(u, TINYF);
    return -logf(-logf(u));
}
__device__ __forceinline__ uint32_t fford(float f) {
    uint32_t b = __float_as_uint(f);
    return (b & 0x80000000u) ? ~b : (b | 0x80000000u);
}
__device__ __forceinline__ float funord(uint32_t u) {
    uint32_t b = (u & 0x80000000u) ? (u ^ 0x80000000u) : ~u;
    return __uint_as_float(b);
}
__device__ __forceinline__ float lrelu(float x) { return x > 0.f ? x : NEG_SLOPE * x; }

// ---------------- kernels ----------------
__global__ void k_init() {
    int i = blockIdx.x * blockDim.x + threadIdx.x;
    if (i < N_NODES) g_cnt[i] = 0;
    if (i == 0) { g_amax = 0ull; g_mlog = 0u; g_sexp = 0.f; }
}

// h1 = x @ Wl1 + bl1 : warp per 8 rows, f32x2 packed FMA, shfl-broadcast x
__global__ void __launch_bounds__(256) k_h1(const float* __restrict__ x,
                                            const float* __restrict__ W,
                                            const float* __restrict__ b) {
    int w = (blockIdx.x * blockDim.x + threadIdx.x) >> 5;
    int lane = threadIdx.x & 31;
    int r0 = w * 8;
    if (r0 >= N_NODES) return;
    int c = lane * 4;
    float4 xr[8];
#pragma unroll
    for (int r = 0; r < 8; r++) xr[r] = *(const float4*)&x[(size_t)(r0 + r) * D + c];
    ull a01[8], a23[8];
#pragma unroll
    for (int r = 0; r < 8; r++) { a01[r] = pk2(0.f, 0.f); a23[r] = pk2(0.f, 0.f); }
#pragma unroll 4
    for (int k4 = 0; k4 < 32; k4++) {
#pragma unroll
        for (int comp = 0; comp < 4; comp++) {
            int k = k4 * 4 + comp;
            ulonglong2 wp = *(const ulonglong2*)&W[k * D + c];
#pragma unroll
            for (int r = 0; r < 8; r++) {
                float xv;
                if (comp == 0) xv = __shfl_sync(0xffffffffu, xr[r].x, k4);
                else if (comp == 1) xv = __shfl_sync(0xffffffffu, xr[r].y, k4);
                else if (comp == 2) xv = __shfl_sync(0xffffffffu, xr[r].z, k4);
                else xv = __shfl_sync(0xffffffffu, xr[r].w, k4);
                ull xx = pk2(xv, xv);
                ffma2(a01[r], xx, wp.x);
                ffma2(a23[r], xx, wp.y);
            }
        }
    }
    float4 bv = *(const float4*)&b[c];
#pragma unroll
    for (int r = 0; r < 8; r++) {
        float4 o;
        upk2(a01[r], o.x, o.y); upk2(a23[r], o.z, o.w);
        o.x += bv.x; o.y += bv.y; o.z += bv.z; o.w += bv.w;
        *(float4*)&g_h1[(size_t)(r0 + r) * D + c] = o;
    }
}

__global__ void k_count(const int* __restrict__ dst) {
    int e = blockIdx.x * blockDim.x + threadIdx.x;
    if (e < N_EDGES) atomicAdd(&g_cnt[dst[e]], 1);
}

// scan pass A: per-block sum of 1024 counts
__global__ void k_scanA() {
    __shared__ int sw[32];
    int i = blockIdx.x * 1024 + threadIdx.x;
    int v = (i < N_NODES) ? g_cnt[i] : 0;
    for (int d2 = 16; d2; d2 >>= 1) v += __shfl_xor_sync(0xffffffffu, v, d2);
    int lane = threadIdx.x & 31, wid = threadIdx.x >> 5;
    if (lane == 0) sw[wid] = v;
    __syncthreads();
    if (threadIdx.x == 0) {
        int t = 0;
        for (int q = 0; q < 32; q++) t += sw[q];
        g_bsum[blockIdx.x] = t;
    }
}

// scan pass B: exclusive scan of 49 block sums (single block of 64)
__global__ void k_scanB() {
    __shared__ int s[64];
    int t = threadIdx.x;
    int v = (t < NB_SCAN) ? g_bsum[t] : 0;
    s[t] = v;
    __syncthreads();
    for (int d2 = 1; d2 < 64; d2 <<= 1) {
        int y = (t >= d2) ? s[t - d2] : 0;
        __syncthreads();
        s[t] += y;
        __syncthreads();
    }
    if (t < NB_SCAN) g_bsum[t] = s[t] - v;   // exclusive
    if (t == 63) g_off[N_NODES] = s[63];     // total
}

// scan pass C: per-block scan + block offset -> g_off, g_cur
__global__ void k_scanC() {
    __shared__ int warp_sums[32];
    int t = threadIdx.x, lane = t & 31, wid = t >> 5;
    int i = blockIdx.x * 1024 + t;
    int v = (i < N_NODES) ? g_cnt[i] : 0;
    int inc = v;
    for (int d2 = 1; d2 < 32; d2 <<= 1) {
        int y = __shfl_up_sync(0xffffffffu, inc, d2);
        if (lane >= d2) inc += y;
    }
    if (lane == 31) warp_sums[wid] = inc;
    __syncthreads();
    if (wid == 0) {
        int ws = warp_sums[lane];
        for (int d2 = 1; d2 < 32; d2 <<= 1) {
            int y = __shfl_up_sync(0xffffffffu, ws, d2);
            if (lane >= d2) ws += y;
        }
        warp_sums[lane] = ws;
    }
    __syncthreads();
    int excl = inc - v + (wid > 0 ? warp_sums[wid - 1] : 0) + g_bsum[blockIdx.x];
    if (i < N_NODES) { g_off[i] = excl; g_cur[i] = excl; }
}

// scatter edges to CSR; also precompute e2 = ea@We2 (scalar) at CSR position
__global__ void k_scatter(const int* __restrict__ src, const int* __restrict__ dst,
                          const float* __restrict__ ea, const float* __restrict__ We2) {
    int e = blockIdx.x * blockDim.x + threadIdx.x;
    if (e >= N_EDGES) return;
    int d = dst[e];
    int s = atomicAdd(&g_cur[d], 1);
    g_csr[s] = e;
    g_csrc[s] = src[e];
    const float4* ea4 = (const float4*)&ea[(size_t)e * DE];
    float t = 0.f;
#pragma unroll
    for (int q = 0; q < 4; q++) {
        float4 v = __ldg(&ea4[q]);
        float4 wv = __ldg((const float4*)&We2[q * 4]);
        t += v.x * wv.x + v.y * wv.y + v.z * wv.z + v.w * wv.w;
    }
    g_e2[s] = t;
}

// layer-1 edge scores: warp per dst row (CSR order, hi loaded once), f32x2 FMA
__global__ void __launch_bounds__(256) k_score1(const float* __restrict__ ea,
                                                const float* __restrict__ We,
                                                const float* __restrict__ att) {
    int gw = (blockIdx.x * blockDim.x + threadIdx.x) >> 5;
    if (gw >= N_NODES) return;
    int lane = threadIdx.x & 31, c = lane * 4;
    ull w01[DE], w23[DE];
#pragma unroll
    for (int k = 0; k < DE; k++) {
        ulonglong2 wp = *(const ulonglong2*)&We[k * D + c];
        w01[k] = wp.x; w23[k] = wp.y;
    }
    float4 av = *(const float4*)&att[c];
    float4 hi = *(const float4*)&g_h1[(size_t)gw * D + c];
    int beg = g_off[gw], end = g_off[gw + 1];
    for (int p = beg; p < end; p++) {
        int j = __ldg(&g_csrc[p]);
        int eid = __ldg(&g_csr[p]);
        float4 hj = *(const float4*)&g_h1[(size_t)j * D + c];
        ull t01 = pk2(hi.x + hj.x, hi.y + hj.y);
        ull t23 = pk2(hi.z + hj.z, hi.w + hj.w);
        const float4* ea4 = (const float4*)(ea + (size_t)eid * DE);
#pragma unroll
        for (int q = 0; q < 4; q++) {
            float4 v = __ldg(&ea4[q]);
            ull vx = pk2(v.x, v.x), vy = pk2(v.y, v.y), vz = pk2(v.z, v.z), vw = pk2(v.w, v.w);
            ffma2(t01, vx, w01[q * 4 + 0]); ffma2(t23, vx, w23[q * 4 + 0]);
            ffma2(t01, vy, w01[q * 4 + 1]); ffma2(t23, vy, w23[q * 4 + 1]);
            ffma2(t01, vz, w01[q * 4 + 2]); ffma2(t23, vz, w23[q * 4 + 2]);
            ffma2(t01, vw, w01[q * 4 + 3]); ffma2(t23, vw, w23[q * 4 + 3]);
        }
        float tx, ty, tz, tw;
        upk2(t01, tx, ty); upk2(t23, tz, tw);
        float s = lrelu(tx) * av.x + lrelu(ty) * av.y + lrelu(tz) * av.z + lrelu(tw) * av.w;
        for (int d2 = 16; d2; d2 >>= 1) s += __shfl_xor_sync(0xffffffffu, s, d2);
        if (lane == 0) g_sc1[p] = s;
    }
}

// layer-1 softmax + aggregation: warp per row; ONE expf per edge (lane-parallel)
__global__ void k_agg1(const float* __restrict__ bias) {
    int gw = (blockIdx.x * blockDim.x + threadIdx.x) >> 5;
    if (gw >= N_NODES) return;
    int lane = threadIdx.x & 31, c = lane * 4;
    int beg = g_off[gw], end = g_off[gw + 1];
    float m = -INFINITY;
    for (int p = beg + lane; p < end; p += 32) m = fmaxf(m, g_sc1[p]);
    for (int d2 = 16; d2; d2 >>= 1) m = fmaxf(m, __shfl_xor_sync(0xffffffffu, m, d2));
    float denl = 0.f;
    float ax = 0.f, ay = 0.f, az = 0.f, aw = 0.f;
    for (int t = beg; t < end; t += 32) {
        int p = t + lane;
        float ex = 0.f; int j = 0;
        if (p < end) { ex = expf(g_sc1[p] - m); j = g_csrc[p]; }
        denl += ex;
        int nn = min(32, end - t);
        for (int q = 0; q < nn; q++) {
            float exq = __shfl_sync(0xffffffffu, ex, q);
            int jq = __shfl_sync(0xffffffffu, j, q);
            float4 hv = *(const float4*)&g_h1[(size_t)jq * D + c];
            ax += exq * hv.x; ay += exq * hv.y; az += exq * hv.z; aw += exq * hv.w;
        }
    }
    for (int d2 = 16; d2; d2 >>= 1) denl += __shfl_xor_sync(0xffffffffu, denl, d2);
    float inv = 1.f / (denl + EPS_);
    float4 bv = *(const float4*)&bias[c];
    float4 o = { ax * inv + bv.x, ay * inv + bv.y, az * inv + bv.z, aw * inv + bv.w };
    *(float4*)&g_lat[(size_t)gw * D + c] = o;
}

// h2 = lat@Wl2 + bl2 ; h3 = lat@Wl3 + bl3 : warp per row
__global__ void k_h23(const float* __restrict__ Wl2, const float* __restrict__ bl2,
                      const float* __restrict__ Wl3, const float* __restrict__ bl3) {
    int gw = (blockIdx.x * blockDim.x + threadIdx.x) >> 5;
    if (gw >= N_NODES) return;
    int lane = threadIdx.x & 31;
    float4 r = *(const float4*)&g_lat[(size_t)gw * D + lane * 4];
    float4 w2 = *(const float4*)&Wl2[lane * 4];
    float p = r.x * w2.x + r.y * w2.y + r.z * w2.z + r.w * w2.w;
    for (int d2 = 16; d2; d2 >>= 1) p += __shfl_xor_sync(0xffffffffu, p, d2);
    if (lane == 0) g_h2[gw] = p + bl2[0];
    float acc = 0.f;
#pragma unroll
    for (int comp = 0; comp < 4; comp++) {
        float v = (comp == 0) ? r.x : (comp == 1) ? r.y : (comp == 2) ? r.z : r.w;
#pragma unroll
        for (int s = 0; s < 32; s++) {
            float lk = __shfl_sync(0xffffffffu, v, s);
            acc += lk * __ldg(&Wl3[(s * 4 + comp) * NACT + lane]);
        }
    }
    g_h3[(size_t)gw * NACT + lane] = acc + bl3[lane];
}

// fused layer-2: scores + softmax + aggregation -> logits. warp per row, lane-parallel edges.
__global__ void k_l2(const float* __restrict__ att2, const float* __restrict__ bias2) {
    int gw = (blockIdx.x * blockDim.x + threadIdx.x) >> 5;
    if (gw >= N_NODES) return;
    int lane = threadIdx.x & 31;
    int beg = g_off[gw], end = g_off[gw + 1];
    float h2i = g_h2[gw];
    float a2 = __ldg(&att2[0]);
    float m = -INFINITY;
    for (int p = beg + lane; p < end; p += 32) {
        float s = lrelu(h2i + __ldg(&g_h2[g_csrc[p]]) + g_e2[p]) * a2;
        m = fmaxf(m, s);
    }
    for (int d2 = 16; d2; d2 >>= 1) m = fmaxf(m, __shfl_xor_sync(0xffffffffu, m, d2));
    float den = 0.f, num = 0.f;
    for (int p = beg + lane; p < end; p += 32) {
        float h2j = __ldg(&g_h2[g_csrc[p]]);
        float s = lrelu(h2i + h2j + g_e2[p]) * a2;
        float ex = expf(s - m);
        den += ex;
        num += ex * h2j;
    }
    for (int d2 = 16; d2; d2 >>= 1) {
        num += __shfl_xor_sync(0xffffffffu, num, d2);
        den += __shfl_xor_sync(0xffffffffu, den, d2);
    }
    if (lane == 0) g_logits[gw] = num / (den + EPS_) + __ldg(&bias2[0]);
}

// node selection pass A: gumbel + argmax(z), max logit
__global__ void k_sel() {
    int i = blockIdx.x * blockDim.x + threadIdx.x;
    unsigned long long key = 0ull;
    unsigned int lk = 0u;
    if (i < N_NODES) {
        float lg = g_logits[i];
        uint32_t k1a, k1b; threefry(0u, 42u, 0u, 0u, k1a, k1b);
        uint32_t bits = jax_bits32(k1a, k1b, (uint32_t)i);
        float z = lg + gumbel_from_bits(bits);
        key = (((unsigned long long)fford(z)) << 32) | (unsigned long long)(0xFFFFFFFFu - (unsigned)i);
        lk = fford(lg);
    }
    for (int d2 = 16; d2; d2 >>= 1) {
        unsigned long long ok = __shfl_xor_sync(0xffffffffu, key, d2); if (ok > key) key = ok;
        unsigned int ol = __shfl_xor_sync(0xffffffffu, lk, d2); if (ol > lk) lk = ol;
    }
    __shared__ unsigned long long sk[8];
    __shared__ unsigned int sl[8];
    int lane = threadIdx.x & 31, w = threadIdx.x >> 5;
    if (lane == 0) { sk[w] = key; sl[w] = lk; }
    __syncthreads();
    if (threadIdx.x == 0) {
        for (int q = 1; q < 8; q++) { if (sk[q] > key) key = sk[q]; if (sl[q] > lk) lk = sl[q]; }
        atomicMax(&g_amax, key);
        atomicMax(&g_mlog, lk);
    }
}

__global__ void k_sumexp() {
    int i = blockIdx.x * blockDim.x + threadIdx.x;
    float ml = funord(g_mlog);
    float v = (i < N_NODES) ? expf(g_logits[i] - ml) : 0.f;
    for (int d2 = 16; d2; d2 >>= 1) v += __shfl_xor_sync(0xffffffffu, v, d2);
    __shared__ float sv[8];
    int lane = threadIdx.x & 31, w = threadIdx.x >> 5;
    if (lane == 0) sv[w] = v;
    __syncthreads();
    if (threadIdx.x == 0) {
        float t = 0;
        for (int q = 0; q < 8; q++) t += sv[q];
        atomicAdd(&g_sexp, t);
    }
}

// final: layer-3 GATv2 only at selected node + action sampling + output
__global__ void k_final(const float* __restrict__ ea, const float* __restrict__ We3,
                        const float* __restrict__ att3, const float* __restrict__ bias3,
                        float* __restrict__ out) {
    __shared__ float s3[4096];
    __shared__ int ssrc[4096];
    int t = threadIdx.x, lane = t & 31, w = t >> 5;
    int sel = (int)(0xFFFFFFFFu - (uint32_t)(g_amax & 0xFFFFFFFFull));
    int beg = g_off[sel], end = g_off[sel + 1];
    int cnt = end - beg;
    if (cnt > 4096) cnt = 4096;
    for (int p = w; p < cnt; p += 8) {
        int eid = g_csr[beg + p];
        int j = g_csrc[beg + p];
        float tt = g_h3[(size_t)sel * NACT + lane] + g_h3[(size_t)j * NACT + lane];
#pragma unroll
        for (int k = 0; k < DE; k++) tt += ea[(size_t)eid * DE + k] * We3[k * NACT + lane];
        tt = lrelu(tt);
        float s = tt * att3[lane];
        for (int d2 = 16; d2; d2 >>= 1) s += __shfl_xor_sync(0xffffffffu, s, d2);
        if (lane == 0) { s3[p] = s; ssrc[p] = j; }
    }
    __syncthreads();
    if (w == 0) {
        float m = -INFINITY;
        for (int p = lane; p < cnt; p += 32) m = fmaxf(m, s3[p]);
        for (int d2 = 16; d2; d2 >>= 1) m = fmaxf(m, __shfl_xor_sync(0xffffffffu, m, d2));
        float den = 0;
        for (int p = lane; p < cnt; p += 32) den += expf(s3[p] - m);
        for (int d2 = 16; d2; d2 >>= 1) den += __shfl_xor_sync(0xffffffffu, den, d2);
        float acc = 0;
        for (int p = 0; p < cnt; p++) {
            float ex = expf(s3[p] - m);
            acc += ex * g_h3[(size_t)ssrc[p] * NACT + lane];
        }
        float logit = acc / (den + EPS_) + bias3[lane];
        uint32_t k2a, k2b; threefry(0u, 42u, 0u, 1u, k2a, k2b);
        uint32_t bits = jax_bits32(k2a, k2b, (uint32_t)lane);
        float z = logit + gumbel_from_bits(bits);
        float zb = z; int ib = lane;
        for (int d2 = 16; d2; d2 >>= 1) {
            float zo = __shfl_xor_sync(0xffffffffu, zb, d2);
            int io = __shfl_xor_sync(0xffffffffu, ib, d2);
            if (zo > zb || (zo == zb && io < ib)) { zb = zo; ib = io; }
        }
        int asel = ib;
        float lm = logit;
        for (int d2 = 16; d2; d2 >>= 1) lm = fmaxf(lm, __shfl_xor_sync(0xffffffffu, lm, d2));
        float se = expf(logit - lm);
        for (int d2 = 16; d2; d2 >>= 1) se += __shfl_xor_sync(0xffffffffu, se, d2);
        float logit_sel = __shfl_sync(0xffffffffu, logit, asel);
        if (lane == 0) {
            float alp = logit_sel - lm - logf(se);
            float ml = funord(g_mlog);
            float nlp = g_logits[sel] - ml - logf(g_sexp);
            out[0] = (float)sel;
            out[1] = (float)asel;
            out[2] = nlp + alp;
        }
    }
}

// ---------------- launch ----------------
extern "C" void kernel_launch(void* const* d_in, const int* in_sizes, int n_in,
                              void* d_out, int out_size) {
    const float* x     = (const float*)d_in[0];
    const int*   ei    = (const int*)  d_in[1];
    const float* ea    = (const float*)d_in[2];
    const float* Wl1   = (const float*)d_in[3];
    const float* bl1   = (const float*)d_in[4];
    const float* We1   = (const float*)d_in[5];
    const float* att1  = (const float*)d_in[6];
    const float* bias1 = (const float*)d_in[7];
    const float* Wl2   = (const float*)d_in[8];
    const float* bl2   = (const float*)d_in[9];
    const float* We2   = (const float*)d_in[10];
    const float* att2  = (const float*)d_in[11];
    const float* bias2 = (const float*)d_in[12];
    const float* Wl3   = (const float*)d_in[13];
    const float* bl3   = (const float*)d_in[14];
    const float* We3   = (const float*)d_in[15];
    const float* att3  = (const float*)d_in[16];
    const float* bias3 = (const float*)d_in[17];
    const int* src = ei;
    const int* dst = ei + N_EDGES;
    float* out = (float*)d_out;

    int ebl = (N_EDGES + 255) / 256;
    int nbl = (N_NODES + 255) / 256;
    int rowbl = (N_NODES + 7) / 8;                       // warp per row, 8 warps/block
    int h1bl = ((N_NODES / 8) * 32 + 255) / 256;         // warp per 8 rows

    k_init<<<nbl, 256>>>();
    k_h1<<<h1bl, 256>>>(x, Wl1, bl1);
    k_count<<<ebl, 256>>>(dst);
    k_scanA<<<NB_SCAN, 1024>>>();
    k_scanB<<<1, 64>>>();
    k_scanC<<<NB_SCAN, 1024>>>();
    k_scatter<<<ebl, 256>>>(src, dst, ea, We2);
    k_score1<<<rowbl, 256>>>(ea, We1, att1);
    k_agg1<<<rowbl, 256>>>(bias1);
    k_h23<<<rowbl, 256>>>(Wl2, bl2, Wl3, bl3);
    k_l2<<<rowbl, 256>>>(att2, bias2);
    k_sel<<<nbl, 256>>>();
    k_sumexp<<<nbl, 256>>>();
    k_final<<<1, 256>>>(ea, We3, att3, bias3, out);
}

// round 7
// speedup vs baseline: 1.6623x; 1.3727x over previous
#include <cuda_runtime.h>
#include <math.h>
#include <stdint.h>

#define N_NODES 50000
#define N_EDGES 800000
#define D 128
#define DE 16
#define NACT 32
#define NEG_SLOPE 0.2f
#define EPS_ 1e-16f
#define TINYF 1.17549435e-38f
#define NB_SCAN 49   // ceil(50000/1024)

// ---------------- scratch ----------------
__device__ float g_h1[N_NODES * D];
__device__ float g_h2[N_NODES];
__device__ float g_h3[N_NODES * NACT];
__device__ float g_e2[N_EDGES];           // ea@We2 scalar, CSR order
__device__ float g_ea1[(size_t)N_EDGES * DE]; // edge_attr re-materialized in CSR order
__device__ int   g_cnt[N_NODES];
__device__ int   g_off[N_NODES + 1];
__device__ int   g_cur[N_NODES];
__device__ int   g_csrc[N_EDGES];         // src node by CSR position
__device__ int   g_bsum[NB_SCAN];
__device__ float g_logits[N_NODES];
__device__ unsigned long long g_amax;
__device__ float g_sexp;

// ---------------- f32x2 packed math ----------------
typedef unsigned long long ull;
__device__ __forceinline__ ull pk2(float a, float b) {
    ull r; asm("mov.b64 %0, {%1, %2};" : "=l"(r) : "f"(a), "f"(b)); return r;
}
__device__ __forceinline__ void upk2(ull v, float& a, float& b) {
    asm("mov.b64 {%0, %1}, %2;" : "=f"(a), "=f"(b) : "l"(v));
}
__device__ __forceinline__ void ffma2(ull& d, ull a, ull b) {
    asm("fma.rn.f32x2 %0, %1, %2, %0;" : "+l"(d) : "l"(a), "l"(b));
}

// ---------------- threefry2x32 (JAX-compatible) ----------------
#define TFR(x0, x1, r) { x0 += x1; x1 = ((x1 << r) | (x1 >> (32 - r))); x1 ^= x0; }
__device__ __forceinline__ void threefry(uint32_t k0, uint32_t k1, uint32_t x0, uint32_t x1,
                                         uint32_t& o0, uint32_t& o1) {
    uint32_t k2 = k0 ^ k1 ^ 0x1BD11BDAu;
    x0 += k0; x1 += k1;
    TFR(x0, x1, 13) TFR(x0, x1, 15) TFR(x0, x1, 26) TFR(x0, x1, 6)  x0 += k1; x1 += k2 + 1u;
    TFR(x0, x1, 17) TFR(x0, x1, 29) TFR(x0, x1, 16) TFR(x0, x1, 24) x0 += k2; x1 += k0 + 2u;
    TFR(x0, x1, 13) TFR(x0, x1, 15) TFR(x0, x1, 26) TFR(x0, x1, 6)  x0 += k0; x1 += k1 + 3u;
    TFR(x0, x1, 17) TFR(x0, x1, 29) TFR(x0, x1, 16) TFR(x0, x1, 24) x0 += k1; x1 += k2 + 4u;
    TFR(x0, x1, 13) TFR(x0, x1, 15) TFR(x0, x1, 26) TFR(x0, x1, 6)  x0 += k2; x1 += k0 + 5u;
    o0 = x0; o1 = x1;
}
__device__ __forceinline__ uint32_t jax_bits32(uint32_t k0, uint32_t k1, uint32_t i) {
    uint32_t o0, o1; threefry(k0, k1, 0u, i, o0, o1); return o0 ^ o1;
}
__device__ __forceinline__ float gumbel_from_bits(uint32_t bits) {
    float u = __uint_as_float((bits >> 9) | 0x3f800000u) - 1.0f;
    u = fmaxf(u, TINYF);
    return -logf(-logf(u));
}
__device__ __forceinline__ uint32_t fford(float f) {
    uint32_t b = __float_as_uint(f);
    return (b & 0x80000000u) ? ~b : (b | 0x80000000u);
}
__device__ __forceinline__ float lrelu(float x) { return x > 0.f ? x : NEG_SLOPE * x; }

// ---------------- kernels ----------------
__global__ void k_init() {
    int i = blockIdx.x * blockDim.x + threadIdx.x;
    if (i < N_NODES) g_cnt[i] = 0;
    if (i == 0) { g_amax = 0ull; g_sexp = 0.f; }
}

// h1 = x @ Wl1 + bl1 : warp per 8 rows, f32x2 packed FMA, shfl-broadcast x
__global__ void __launch_bounds__(256) k_h1(const float* __restrict__ x,
                                            const float* __restrict__ W,
                                            const float* __restrict__ b) {
    int w = (blockIdx.x * blockDim.x + threadIdx.x) >> 5;
    int lane = threadIdx.x & 31;
    int r0 = w * 8;
    if (r0 >= N_NODES) return;
    int c = lane * 4;
    float4 xr[8];
#pragma unroll
    for (int r = 0; r < 8; r++) xr[r] = *(const float4*)&x[(size_t)(r0 + r) * D + c];
    ull a01[8], a23[8];
#pragma unroll
    for (int r = 0; r < 8; r++) { a01[r] = pk2(0.f, 0.f); a23[r] = pk2(0.f, 0.f); }
#pragma unroll 4
    for (int k4 = 0; k4 < 32; k4++) {
#pragma unroll
        for (int comp = 0; comp < 4; comp++) {
            int k = k4 * 4 + comp;
            ulonglong2 wp = *(const ulonglong2*)&W[k * D + c];
#pragma unroll
            for (int r = 0; r < 8; r++) {
                float xv;
                if (comp == 0) xv = __shfl_sync(0xffffffffu, xr[r].x, k4);
                else if (comp == 1) xv = __shfl_sync(0xffffffffu, xr[r].y, k4);
                else if (comp == 2) xv = __shfl_sync(0xffffffffu, xr[r].z, k4);
                else xv = __shfl_sync(0xffffffffu, xr[r].w, k4);
                ull xx = pk2(xv, xv);
                ffma2(a01[r], xx, wp.x);
                ffma2(a23[r], xx, wp.y);
            }
        }
    }
    float4 bv = *(const float4*)&b[c];
#pragma unroll
    for (int r = 0; r < 8; r++) {
        float4 o;
        upk2(a01[r], o.x, o.y); upk2(a23[r], o.z, o.w);
        o.x += bv.x; o.y += bv.y; o.z += bv.z; o.w += bv.w;
        *(float4*)&g_h1[(size_t)(r0 + r) * D + c] = o;
    }
}

__global__ void k_count(const int* __restrict__ dst) {
    int e = blockIdx.x * blockDim.x + threadIdx.x;
    if (e < N_EDGES) atomicAdd(&g_cnt[dst[e]], 1);
}

__global__ void k_scanA() {
    __shared__ int sw[32];
    int i = blockIdx.x * 1024 + threadIdx.x;
    int v = (i < N_NODES) ? g_cnt[i] : 0;
    for (int d2 = 16; d2; d2 >>= 1) v += __shfl_xor_sync(0xffffffffu, v, d2);
    int lane = threadIdx.x & 31, wid = threadIdx.x >> 5;
    if (lane == 0) sw[wid] = v;
    __syncthreads();
    if (threadIdx.x == 0) {
        int t = 0;
        for (int q = 0; q < 32; q++) t += sw[q];
        g_bsum[blockIdx.x] = t;
    }
}

__global__ void k_scanB() {
    __shared__ int s[64];
    int t = threadIdx.x;
    int v = (t < NB_SCAN) ? g_bsum[t] : 0;
    s[t] = v;
    __syncthreads();
    for (int d2 = 1; d2 < 64; d2 <<= 1) {
        int y = (t >= d2) ? s[t - d2] : 0;
        __syncthreads();
        s[t] += y;
        __syncthreads();
    }
    if (t < NB_SCAN) g_bsum[t] = s[t] - v;
    if (t == 63) g_off[N_NODES] = s[63];
}

__global__ void k_scanC() {
    __shared__ int warp_sums[32];
    int t = threadIdx.x, lane = t & 31, wid = t >> 5;
    int i = blockIdx.x * 1024 + t;
    int v = (i < N_NODES) ? g_cnt[i] : 0;
    int inc = v;
    for (int d2 = 1; d2 < 32; d2 <<= 1) {
        int y = __shfl_up_sync(0xffffffffu, inc, d2);
        if (lane >= d2) inc += y;
    }
    if (lane == 31) warp_sums[wid] = inc;
    __syncthreads();
    if (wid == 0) {
        int ws = warp_sums[lane];
        for (int d2 = 1; d2 < 32; d2 <<= 1) {
            int y = __shfl_up_sync(0xffffffffu, ws, d2);
            if (lane >= d2) ws += y;
        }
        warp_sums[lane] = ws;
    }
    __syncthreads();
    int excl = inc - v + (wid > 0 ? warp_sums[wid - 1] : 0) + g_bsum[blockIdx.x];
    if (i < N_NODES) { g_off[i] = excl; g_cur[i] = excl; }
}

// scatter: CSR build + e2 = ea@We2 scalar + ea re-materialized in CSR order
__global__ void k_scatter(const int* __restrict__ src, const int* __restrict__ dst,
                          const float* __restrict__ ea, const float* __restrict__ We2) {
    int e = blockIdx.x * blockDim.x + threadIdx.x;
    if (e >= N_EDGES) return;
    int d = dst[e];
    int s = atomicAdd(&g_cur[d], 1);
    g_csrc[s] = src[e];
    const float4* ea4 = (const float4*)&ea[(size_t)e * DE];
    float4* eo = (float4*)&g_ea1[(size_t)s * DE];
    float t = 0.f;
#pragma unroll
    for (int q = 0; q < 4; q++) {
        float4 v = __ldg(&ea4[q]);
        float4 wv = __ldg((const float4*)&We2[q * 4]);
        t += v.x * wv.x + v.y * wv.y + v.z * wv.z + v.w * wv.w;
        eo[q] = v;
    }
    g_e2[s] = t;
}

// fused layer-1: scores + exp + aggregation + h2/h3 projections. warp per dst row.
// No max-subtraction (scores O(1); softmax invariant). h[src] gathered ONCE.
__global__ void __launch_bounds__(256) k_l1(const float* __restrict__ We,
                                            const float* __restrict__ att,
                                            const float* __restrict__ bias1,
                                            const float* __restrict__ Wl2,
                                            const float* __restrict__ bl2,
                                            const float* __restrict__ Wl3,
                                            const float* __restrict__ bl3) {
    int gw = (blockIdx.x * blockDim.x + threadIdx.x) >> 5;
    if (gw >= N_NODES) return;
    int lane = threadIdx.x & 31, c = lane * 4;
    ull w01[DE], w23[DE];
#pragma unroll
    for (int k = 0; k < DE; k++) {
        ulonglong2 wp = *(const ulonglong2*)&We[k * D + c];
        w01[k] = wp.x; w23[k] = wp.y;
    }
    float4 av = *(const float4*)&att[c];
    float4 hi = *(const float4*)&g_h1[(size_t)gw * D + c];
    int beg = g_off[gw], end = g_off[gw + 1];
    float den = 0.f, ax = 0.f, ay = 0.f, az = 0.f, aw = 0.f;
    for (int p = beg; p < end; p++) {
        int j = __ldg(&g_csrc[p]);
        float4 hj = *(const float4*)&g_h1[(size_t)j * D + c];
        ull t01 = pk2(hi.x + hj.x, hi.y + hj.y);
        ull t23 = pk2(hi.z + hj.z, hi.w + hj.w);
        const float4* ea4 = (const float4*)&g_ea1[(size_t)p * DE];
#pragma unroll
        for (int q = 0; q < 4; q++) {
            float4 v = __ldg(&ea4[q]);
            ull vx = pk2(v.x, v.x), vy = pk2(v.y, v.y), vz = pk2(v.z, v.z), vw = pk2(v.w, v.w);
            ffma2(t01, vx, w01[q * 4 + 0]); ffma2(t23, vx, w23[q * 4 + 0]);
            ffma2(t01, vy, w01[q * 4 + 1]); ffma2(t23, vy, w23[q * 4 + 1]);
            ffma2(t01, vz, w01[q * 4 + 2]); ffma2(t23, vz, w23[q * 4 + 2]);
            ffma2(t01, vw, w01[q * 4 + 3]); ffma2(t23, vw, w23[q * 4 + 3]);
        }
        float tx, ty, tz, tw;
        upk2(t01, tx, ty); upk2(t23, tz, tw);
        float s = lrelu(tx) * av.x + lrelu(ty) * av.y + lrelu(tz) * av.z + lrelu(tw) * av.w;
        for (int d2 = 16; d2; d2 >>= 1) s += __shfl_xor_sync(0xffffffffu, s, d2);
        float ex = expf(s);   // lane-uniform; costs one warp MUFU sequence
        den += ex;
        ax += ex * hj.x; ay += ex * hj.y; az += ex * hj.z; aw += ex * hj.w;
    }
    float inv = 1.f / (den + EPS_);
    float4 bv = *(const float4*)&bias1[c];
    float lx = ax * inv + bv.x, ly = ay * inv + bv.y;
    float lz = az * inv + bv.z, lw = aw * inv + bv.w;
    // h2 = lat . Wl2 + bl2
    float4 w2 = *(const float4*)&Wl2[c];
    float p2 = lx * w2.x + ly * w2.y + lz * w2.z + lw * w2.w;
    for (int d2 = 16; d2; d2 >>= 1) p2 += __shfl_xor_sync(0xffffffffu, p2, d2);
    if (lane == 0) g_h2[gw] = p2 + __ldg(&bl2[0]);
    // h3 = lat @ Wl3 + bl3 (lane = output col)
    float acc = 0.f;
#pragma unroll
    for (int comp = 0; comp < 4; comp++) {
        float v = (comp == 0) ? lx : (comp == 1) ? ly : (comp == 2) ? lz : lw;
#pragma unroll
        for (int s2 = 0; s2 < 32; s2++) {
            float lk = __shfl_sync(0xffffffffu, v, s2);
            acc += lk * __ldg(&Wl3[(s2 * 4 + comp) * NACT + lane]);
        }
    }
    g_h3[(size_t)gw * NACT + lane] = acc + __ldg(&bl3[lane]);
}

// fused layer-2: single-pass (no max-sub) scores + softmax + aggregation -> logits
__global__ void k_l2(const float* __restrict__ att2, const float* __restrict__ bias2) {
    int gw = (blockIdx.x * blockDim.x + threadIdx.x) >> 5;
    if (gw >= N_NODES) return;
    int lane = threadIdx.x & 31;
    int beg = g_off[gw], end = g_off[gw + 1];
    float h2i = g_h2[gw];
    float a2 = __ldg(&att2[0]);
    float den = 0.f, num = 0.f;
    for (int p = beg + lane; p < end; p += 32) {
        float h2j = __ldg(&g_h2[g_csrc[p]]);
        float s = lrelu(h2i + h2j + g_e2[p]) * a2;
        float ex = expf(s);
        den += ex;
        num += ex * h2j;
    }
    for (int d2 = 16; d2; d2 >>= 1) {
        num += __shfl_xor_sync(0xffffffffu, num, d2);
        den += __shfl_xor_sync(0xffffffffu, den, d2);
    }
    if (lane == 0) g_logits[gw] = num / (den + EPS_) + __ldg(&bias2[0]);
}

// node selection: gumbel argmax + sum exp(logit) (no max-sub) in one pass
__global__ void k_sel() {
    int i = blockIdx.x * blockDim.x + threadIdx.x;
    unsigned long long key = 0ull;
    float ex = 0.f;
    if (i < N_NODES) {
        float lg = g_logits[i];
        uint32_t k1a, k1b; threefry(0u, 42u, 0u, 0u, k1a, k1b);
        uint32_t bits = jax_bits32(k1a, k1b, (uint32_t)i);
        float z = lg + gumbel_from_bits(bits);
        key = (((unsigned long long)fford(z)) << 32) | (unsigned long long)(0xFFFFFFFFu - (unsigned)i);
        ex = expf(lg);
    }
    for (int d2 = 16; d2; d2 >>= 1) {
        unsigned long long ok = __shfl_xor_sync(0xffffffffu, key, d2); if (ok > key) key = ok;
        ex += __shfl_xor_sync(0xffffffffu, ex, d2);
    }
    __shared__ unsigned long long sk[8];
    __shared__ float sv[8];
    int lane = threadIdx.x & 31, w = threadIdx.x >> 5;
    if (lane == 0) { sk[w] = key; sv[w] = ex; }
    __syncthreads();
    if (threadIdx.x == 0) {
        float t = 0.f;
        for (int q = 0; q < 8; q++) { if (sk[q] > key) key = sk[q]; t += sv[q]; }
        atomicMax(&g_amax, key);
        atomicAdd(&g_sexp, t);
    }
}

// final: layer-3 GATv2 only at selected node + action sampling + output
__global__ void k_final(const float* __restrict__ We3, const float* __restrict__ att3,
                        const float* __restrict__ bias3, float* __restrict__ out) {
    __shared__ float s3[4096];
    __shared__ int ssrc[4096];
    int t = threadIdx.x, lane = t & 31, w = t >> 5;
    int sel = (int)(0xFFFFFFFFu - (uint32_t)(g_amax & 0xFFFFFFFFull));
    int beg = g_off[sel], end = g_off[sel + 1];
    int cnt = end - beg;
    if (cnt > 4096) cnt = 4096;
    for (int p = w; p < cnt; p += 8) {
        int j = g_csrc[beg + p];
        float tt = g_h3[(size_t)sel * NACT + lane] + g_h3[(size_t)j * NACT + lane];
        const float* eap = &g_ea1[(size_t)(beg + p) * DE];
#pragma unroll
        for (int k = 0; k < DE; k++) tt += eap[k] * We3[k * NACT + lane];
        tt = lrelu(tt);
        float s = tt * att3[lane];
        for (int d2 = 16; d2; d2 >>= 1) s += __shfl_xor_sync(0xffffffffu, s, d2);
        if (lane == 0) { s3[p] = s; ssrc[p] = j; }
    }
    __syncthreads();
    if (w == 0) {
        float m = -INFINITY;
        for (int p = lane; p < cnt; p += 32) m = fmaxf(m, s3[p]);
        for (int d2 = 16; d2; d2 >>= 1) m = fmaxf(m, __shfl_xor_sync(0xffffffffu, m, d2));
        float den = 0;
        for (int p = lane; p < cnt; p += 32) den += expf(s3[p] - m);
        for (int d2 = 16; d2; d2 >>= 1) den += __shfl_xor_sync(0xffffffffu, den, d2);
        float acc = 0;
        for (int p = 0; p < cnt; p++) {
            float ex = expf(s3[p] - m);
            acc += ex * g_h3[(size_t)ssrc[p] * NACT + lane];
        }
        float logit = acc / (den + EPS_) + bias3[lane];
        uint32_t k2a, k2b; threefry(0u, 42u, 0u, 1u, k2a, k2b);
        uint32_t bits = jax_bits32(k2a, k2b, (uint32_t)lane);
        float z = logit + gumbel_from_bits(bits);
        float zb = z; int ib = lane;
        for (int d2 = 16; d2; d2 >>= 1) {
            float zo = __shfl_xor_sync(0xffffffffu, zb, d2);
            int io = __shfl_xor_sync(0xffffffffu, ib, d2);
            if (zo > zb || (zo == zb && io < ib)) { zb = zo; ib = io; }
        }
        int asel = ib;
        float lm = logit;
        for (int d2 = 16; d2; d2 >>= 1) lm = fmaxf(lm, __shfl_xor_sync(0xffffffffu, lm, d2));
        float se = expf(logit - lm);
        for (int d2 = 16; d2; d2 >>= 1) se += __shfl_xor_sync(0xffffffffu, se, d2);
        float logit_sel = __shfl_sync(0xffffffffu, logit, asel);
        if (lane == 0) {
            float alp = logit_sel - lm - logf(se);
            float nlp = g_logits[sel] - logf(g_sexp);
            out[0] = (float)sel;
            out[1] = (float)asel;
            out[2] = nlp + alp;
        }
    }
}

// ---------------- launch ----------------
extern "C" void kernel_launch(void* const* d_in, const int* in_sizes, int n_in,
                              void* d_out, int out_size) {
    const float* x     = (const float*)d_in[0];
    const int*   ei    = (const int*)  d_in[1];
    const float* ea    = (const float*)d_in[2];
    const float* Wl1   = (const float*)d_in[3];
    const float* bl1   = (const float*)d_in[4];
    const float* We1   = (const float*)d_in[5];
    const float* att1  = (const float*)d_in[6];
    const float* bias1 = (const float*)d_in[7];
    const float* Wl2   = (const float*)d_in[8];
    const float* bl2   = (const float*)d_in[9];
    const float* We2   = (const float*)d_in[10];
    const float* att2  = (const float*)d_in[11];
    const float* bias2 = (const float*)d_in[12];
    const float* Wl3   = (const float*)d_in[13];
    const float* bl3   = (const float*)d_in[14];
    const float* We3   = (const float*)d_in[15];
    const float* att3  = (const float*)d_in[16];
    const float* bias3 = (const float*)d_in[17];
    const int* src = ei;
    const int* dst = ei + N_EDGES;
    float* out = (float*)d_out;

    int ebl = (N_EDGES + 255) / 256;
    int nbl = (N_NODES + 255) / 256;
    int rowbl = (N_NODES + 7) / 8;                       // warp per row, 8 warps/block
    int h1bl = ((N_NODES / 8) * 32 + 255) / 256;         // warp per 8 rows

    k_init<<<nbl, 256>>>();
    k_h1<<<h1bl, 256>>>(x, Wl1, bl1);
    k_count<<<ebl, 256>>>(dst);
    k_scanA<<<NB_SCAN, 1024>>>();
    k_scanB<<<1, 64>>>();
    k_scanC<<<NB_SCAN, 1024>>>();
    k_scatter<<<ebl, 256>>>(src, dst, ea, We2);
    k_l1<<<rowbl, 256>>>(We1, att1, bias1, Wl2, bl2, Wl3, bl3);
    k_l2<<<rowbl, 256>>>(att2, bias2);
    k_sel<<<nbl, 256>>>();
    k_final<<<1, 256>>>(We3, att3, bias3, out);
}

// round 9
// speedup vs baseline: 1.8200x; 1.0948x over previous
#include <cuda_runtime.h>
#include <math.h>
#include <stdint.h>

#define N_NODES 50000
#define N_EDGES 800000
#define D 128
#define DE 16
#define NACT 32
#define NEG_SLOPE 0.2f
#define EPS_ 1e-16f
#define TINYF 1.17549435e-38f
#define NB_SCAN 49   // ceil(50000/1024)

// ---------------- scratch ----------------
__device__ float g_h1[N_NODES * D];
__device__ float g_h2[N_NODES];
__device__ float g_h3[N_NODES * NACT];
__device__ float g_e2[N_EDGES];               // ea@We2 scalar, CSR order
__device__ float g_ea1[(size_t)N_EDGES * DE]; // edge_attr in CSR order
__device__ int   g_cnt[N_NODES];
__device__ int   g_off[N_NODES + 1];
__device__ int   g_cur[N_NODES];
__device__ int   g_csrc[N_EDGES];             // src node by CSR position
__device__ int   g_bsum[NB_SCAN];
__device__ float g_logits[N_NODES];
__device__ unsigned long long g_amax;
__device__ float g_sexp;

// ---------------- f32x2 packed math ----------------
typedef unsigned long long ull;
__device__ __forceinline__ ull pk2(float a, float b) {
    ull r; asm("mov.b64 %0, {%1, %2};" : "=l"(r) : "f"(a), "f"(b)); return r;
}
__device__ __forceinline__ void upk2(ull v, float& a, float& b) {
    asm("mov.b64 {%0, %1}, %2;" : "=f"(a), "=f"(b) : "l"(v));
}
__device__ __forceinline__ void ffma2(ull& d, ull a, ull b) {
    asm("fma.rn.f32x2 %0, %1, %2, %0;" : "+l"(d) : "l"(a), "l"(b));
}

// ---------------- threefry2x32 (JAX-compatible) ----------------
#define TFR(x0, x1, r) { x0 += x1; x1 = ((x1 << r) | (x1 >> (32 - r))); x1 ^= x0; }
__device__ __forceinline__ void threefry(uint32_t k0, uint32_t k1, uint32_t x0, uint32_t x1,
                                         uint32_t& o0, uint32_t& o1) {
    uint32_t k2 = k0 ^ k1 ^ 0x1BD11BDAu;
    x0 += k0; x1 += k1;
    TFR(x0, x1, 13) TFR(x0, x1, 15) TFR(x0, x1, 26) TFR(x0, x1, 6)  x0 += k1; x1 += k2 + 1u;
    TFR(x0, x1, 17) TFR(x0, x1, 29) TFR(x0, x1, 16) TFR(x0, x1, 24) x0 += k2; x1 += k0 + 2u;
    TFR(x0, x1, 13) TFR(x0, x1, 15) TFR(x0, x1, 26) TFR(x0, x1, 6)  x0 += k0; x1 += k1 + 3u;
    TFR(x0, x1, 17) TFR(x0, x1, 29) TFR(x0, x1, 16) TFR(x0, x1, 24) x0 += k1; x1 += k2 + 4u;
    TFR(x0, x1, 13) TFR(x0, x1, 15) TFR(x0, x1, 26) TFR(x0, x1, 6)  x0 += k2; x1 += k0 + 5u;
    o0 = x0; o1 = x1;
}
__device__ __forceinline__ uint32_t jax_bits32(uint32_t k0, uint32_t k1, uint32_t i) {
    uint32_t o0, o1; threefry(k0, k1, 0u, i, o0, o1); return o0 ^ o1;
}
__device__ __forceinline__ float gumbel_from_bits(uint32_t bits) {
    float u = __uint_as_float((bits >> 9) | 0x3f800000u) - 1.0f;
    u = fmaxf(u, TINYF);
    return -logf(-logf(u));
}
__device__ __forceinline__ uint32_t fford(float f) {
    uint32_t b = __float_as_uint(f);
    return (b & 0x80000000u) ? ~b : (b | 0x80000000u);
}
__device__ __forceinline__ float lrelu(float x) { return x > 0.f ? x : NEG_SLOPE * x; }

// ---------------- kernels ----------------
__global__ void k_init() {
    int i = blockIdx.x * blockDim.x + threadIdx.x;
    if (i < N_NODES) g_cnt[i] = 0;
    if (i == 0) { g_amax = 0ull; g_sexp = 0.f; }
}

// h1 = x @ Wl1 + bl1 : warp per 8 rows, f32x2 packed FMA, shfl-broadcast x
__global__ void __launch_bounds__(256) k_h1(const float* __restrict__ x,
                                            const float* __restrict__ W,
                                            const float* __restrict__ b) {
    int w = (blockIdx.x * blockDim.x + threadIdx.x) >> 5;
    int lane = threadIdx.x & 31;
    int r0 = w * 8;
    if (r0 >= N_NODES) return;
    int c = lane * 4;
    float4 xr[8];
#pragma unroll
    for (int r = 0; r < 8; r++) xr[r] = *(const float4*)&x[(size_t)(r0 + r) * D + c];
    ull a01[8], a23[8];
#pragma unroll
    for (int r = 0; r < 8; r++) { a01[r] = pk2(0.f, 0.f); a23[r] = pk2(0.f, 0.f); }
#pragma unroll 4
    for (int k4 = 0; k4 < 32; k4++) {
#pragma unroll
        for (int comp = 0; comp < 4; comp++) {
            int k = k4 * 4 + comp;
            ulonglong2 wp = *(const ulonglong2*)&W[k * D + c];
#pragma unroll
            for (int r = 0; r < 8; r++) {
                float xv;
                if (comp == 0) xv = __shfl_sync(0xffffffffu, xr[r].x, k4);
                else if (comp == 1) xv = __shfl_sync(0xffffffffu, xr[r].y, k4);
                else if (comp == 2) xv = __shfl_sync(0xffffffffu, xr[r].z, k4);
                else xv = __shfl_sync(0xffffffffu, xr[r].w, k4);
                ull xx = pk2(xv, xv);
                ffma2(a01[r], xx, wp.x);
                ffma2(a23[r], xx, wp.y);
            }
        }
    }
    float4 bv = *(const float4*)&b[c];
#pragma unroll
    for (int r = 0; r < 8; r++) {
        float4 o;
        upk2(a01[r], o.x, o.y); upk2(a23[r], o.z, o.w);
        o.x += bv.x; o.y += bv.y; o.z += bv.z; o.w += bv.w;
        *(float4*)&g_h1[(size_t)(r0 + r) * D + c] = o;
    }
}

__global__ void k_count(const int* __restrict__ dst) {
    int e = blockIdx.x * blockDim.x + threadIdx.x;
    if (e < N_EDGES) atomicAdd(&g_cnt[dst[e]], 1);
}

__global__ void k_scanA() {
    __shared__ int sw[32];
    int i = blockIdx.x * 1024 + threadIdx.x;
    int v = (i < N_NODES) ? g_cnt[i] : 0;
    for (int d2 = 16; d2; d2 >>= 1) v += __shfl_xor_sync(0xffffffffu, v, d2);
    int lane = threadIdx.x & 31, wid = threadIdx.x >> 5;
    if (lane == 0) sw[wid] = v;
    __syncthreads();
    if (threadIdx.x == 0) {
        int t = 0;
        for (int q = 0; q < 32; q++) t += sw[q];
        g_bsum[blockIdx.x] = t;
    }
}

__global__ void k_scanB() {
    __shared__ int s[64];
    int t = threadIdx.x;
    int v = (t < NB_SCAN) ? g_bsum[t] : 0;
    s[t] = v;
    __syncthreads();
    for (int d2 = 1; d2 < 64; d2 <<= 1) {
        int y = (t >= d2) ? s[t - d2] : 0;
        __syncthreads();
        s[t] += y;
        __syncthreads();
    }
    if (t < NB_SCAN) g_bsum[t] = s[t] - v;
    if (t == 63) g_off[N_NODES] = s[63];
}

__global__ void k_scanC() {
    __shared__ int warp_sums[32];
    int t = threadIdx.x, lane = t & 31, wid = t >> 5;
    int i = blockIdx.x * 1024 + t;
    int v = (i < N_NODES) ? g_cnt[i] : 0;
    int inc = v;
    for (int d2 = 1; d2 < 32; d2 <<= 1) {
        int y = __shfl_up_sync(0xffffffffu, inc, d2);
        if (lane >= d2) inc += y;
    }
    if (lane == 31) warp_sums[wid] = inc;
    __syncthreads();
    if (wid == 0) {
        int ws = warp_sums[lane];
        for (int d2 = 1; d2 < 32; d2 <<= 1) {
            int y = __shfl_up_sync(0xffffffffu, ws, d2);
            if (lane >= d2) ws += y;
        }
        warp_sums[lane] = ws;
    }
    __syncthreads();
    int excl = inc - v + (wid > 0 ? warp_sums[wid - 1] : 0) + g_bsum[blockIdx.x];
    if (i < N_NODES) { g_off[i] = excl; g_cur[i] = excl; }
}

// scatter: CSR build + e2 = ea@We2 scalar + ea re-materialized in CSR order
__global__ void k_scatter(const int* __restrict__ src, const int* __restrict__ dst,
                          const float* __restrict__ ea, const float* __restrict__ We2) {
    int e = blockIdx.x * blockDim.x + threadIdx.x;
    if (e >= N_EDGES) return;
    int d = dst[e];
    int s = atomicAdd(&g_cur[d], 1);
    g_csrc[s] = src[e];
    const float4* ea4 = (const float4*)&ea[(size_t)e * DE];
    float4* eo = (float4*)&g_ea1[(size_t)s * DE];
    float t = 0.f;
#pragma unroll
    for (int q = 0; q < 4; q++) {
        float4 v = __ldg(&ea4[q]);
        float4 wv = __ldg((const float4*)&We2[q * 4]);
        t += v.x * wv.x + v.y * wv.y + v.z * wv.z + v.w * wv.w;
        eo[q] = v;
    }
    g_e2[s] = t;
}

// per-lane partial score for one edge (before warp reduction)
__device__ __forceinline__ float escore(const float4& hi, const float4& hj,
                                        const float4* __restrict__ ea4,
                                        const ull* __restrict__ w01,
                                        const ull* __restrict__ w23,
                                        const float4& av) {
    ull t01 = pk2(hi.x + hj.x, hi.y + hj.y);
    ull t23 = pk2(hi.z + hj.z, hi.w + hj.w);
#pragma unroll
    for (int q = 0; q < 4; q++) {
        float4 v = __ldg(&ea4[q]);
        ull vx = pk2(v.x, v.x), vy = pk2(v.y, v.y), vz = pk2(v.z, v.z), vw = pk2(v.w, v.w);
        ffma2(t01, vx, w01[q * 4 + 0]); ffma2(t23, vx, w23[q * 4 + 0]);
        ffma2(t01, vy, w01[q * 4 + 1]); ffma2(t23, vy, w23[q * 4 + 1]);
        ffma2(t01, vz, w01[q * 4 + 2]); ffma2(t23, vz, w23[q * 4 + 2]);
        ffma2(t01, vw, w01[q * 4 + 3]); ffma2(t23, vw, w23[q * 4 + 3]);
    }
    float tx, ty, tz, tw;
    upk2(t01, tx, ty); upk2(t23, tz, tw);
    return lrelu(tx) * av.x + lrelu(ty) * av.y + lrelu(tz) * av.z + lrelu(tw) * av.w;
}

// fused layer-1: scores + exp + aggregation + h2/h3 projections. warp per dst row.
// 4-edge software pipeline: batched gathers + interleaved shfl reductions.
__global__ void __launch_bounds__(128, 4) k_l1(const float* __restrict__ We,
                                               const float* __restrict__ att,
                                               const float* __restrict__ bias1,
                                               const float* __restrict__ Wl2,
                                               const float* __restrict__ bl2,
                                               const float* __restrict__ Wl3,
                                               const float* __restrict__ bl3) {
    int gw = (blockIdx.x * blockDim.x + threadIdx.x) >> 5;
    if (gw >= N_NODES) return;
    int lane = threadIdx.x & 31, c = lane * 4;
    ull w01[DE], w23[DE];
#pragma unroll
    for (int k = 0; k < DE; k++) {
        ulonglong2 wp = *(const ulonglong2*)&We[k * D + c];
        w01[k] = wp.x; w23[k] = wp.y;
    }
    float4 av = *(const float4*)&att[c];
    float4 hi = *(const float4*)&g_h1[(size_t)gw * D + c];
    int beg = g_off[gw], end = g_off[gw + 1];
    float den = 0.f, ax = 0.f, ay = 0.f, az = 0.f, aw = 0.f;
    int p = beg;
    for (; p + 4 <= end; p += 4) {
        int j0 = __ldg(&g_csrc[p + 0]);
        int j1 = __ldg(&g_csrc[p + 1]);
        int j2 = __ldg(&g_csrc[p + 2]);
        int j3 = __ldg(&g_csrc[p + 3]);
        float4 h0 = *(const float4*)&g_h1[(size_t)j0 * D + c];
        float4 h1 = *(const float4*)&g_h1[(size_t)j1 * D + c];
        float4 h2 = *(const float4*)&g_h1[(size_t)j2 * D + c];
        float4 h3 = *(const float4*)&g_h1[(size_t)j3 * D + c];
        const float4* A = (const float4*)&g_ea1[(size_t)p * DE];
        float s0 = escore(hi, h0, A + 0,  w01, w23, av);
        float s1 = escore(hi, h1, A + 4,  w01, w23, av);
        float s2 = escore(hi, h2, A + 8,  w01, w23, av);
        float s3 = escore(hi, h3, A + 12, w01, w23, av);
#pragma unroll
        for (int d2 = 16; d2; d2 >>= 1) {
            s0 += __shfl_xor_sync(0xffffffffu, s0, d2);
            s1 += __shfl_xor_sync(0xffffffffu, s1, d2);
            s2 += __shfl_xor_sync(0xffffffffu, s2, d2);
            s3 += __shfl_xor_sync(0xffffffffu, s3, d2);
        }
        float e0 = __expf(s0), e1 = __expf(s1), e2 = __expf(s2), e3 = __expf(s3);
        den += (e0 + e1) + (e2 + e3);
        ax += e0 * h0.x + e1 * h1.x + e2 * h2.x + e3 * h3.x;
        ay += e0 * h0.y + e1 * h1.y + e2 * h2.y + e3 * h3.y;
        az += e0 * h0.z + e1 * h1.z + e2 * h2.z + e3 * h3.z;
        aw += e0 * h0.w + e1 * h1.w + e2 * h2.w + e3 * h3.w;
    }
    for (; p < end; p++) {
        int j = __ldg(&g_csrc[p]);
        float4 hj = *(const float4*)&g_h1[(size_t)j * D + c];
        float s = escore(hi, hj, (const float4*)&g_ea1[(size_t)p * DE], w01, w23, av);
#pragma unroll
        for (int d2 = 16; d2; d2 >>= 1) s += __shfl_xor_sync(0xffffffffu, s, d2);
        float ex = __expf(s);
        den += ex;
        ax += ex * hj.x; ay += ex * hj.y; az += ex * hj.z; aw += ex * hj.w;
    }
    float inv = 1.f / (den + EPS_);
    float4 bv = *(const float4*)&bias1[c];
    float lx = ax * inv + bv.x, ly = ay * inv + bv.y;
    float lz = az * inv + bv.z, lw = aw * inv + bv.w;
    // h2 = lat . Wl2 + bl2
    float4 w2 = *(const float4*)&Wl2[c];
    float p2 = lx * w2.x + ly * w2.y + lz * w2.z + lw * w2.w;
#pragma unroll
    for (int d2 = 16; d2; d2 >>= 1) p2 += __shfl_xor_sync(0xffffffffu, p2, d2);
    if (lane == 0) g_h2[gw] = p2 + __ldg(&bl2[0]);
    // h3 = lat @ Wl3 + bl3 (lane = output col)
    float acc = 0.f;
#pragma unroll
    for (int comp = 0; comp < 4; comp++) {
        float v = (comp == 0) ? lx : (comp == 1) ? ly : (comp == 2) ? lz : lw;
#pragma unroll
        for (int s2 = 0; s2 < 32; s2++) {
            float lk = __shfl_sync(0xffffffffu, v, s2);
            acc += lk * __ldg(&Wl3[(s2 * 4 + comp) * NACT + lane]);
        }
    }
    g_h3[(size_t)gw * NACT + lane] = acc + __ldg(&bl3[lane]);
}

// fused layer-2: single-pass scores + softmax + aggregation -> logits
__global__ void k_l2(const float* __restrict__ att2, const float* __restrict__ bias2) {
    int gw = (blockIdx.x * blockDim.x + threadIdx.x) >> 5;
    if (gw >= N_NODES) return;
    int lane = threadIdx.x & 31;
    int beg = g_off[gw], end = g_off[gw + 1];
    float h2i = g_h2[gw];
    float a2 = __ldg(&att2[0]);
    float den = 0.f, num = 0.f;
    for (int p = beg + lane; p < end; p += 32) {
        float h2j = __ldg(&g_h2[g_csrc[p]]);
        float s = lrelu(h2i + h2j + g_e2[p]) * a2;
        float ex = __expf(s);
        den += ex;
        num += ex * h2j;
    }
#pragma unroll
    for (int d2 = 16; d2; d2 >>= 1) {
        num += __shfl_xor_sync(0xffffffffu, num, d2);
        den += __shfl_xor_sync(0xffffffffu, den, d2);
    }
    if (lane == 0) g_logits[gw] = num / (den + EPS_) + __ldg(&bias2[0]);
}

// node selection: gumbel argmax + sum exp(logit) in one pass
__global__ void k_sel() {
    int i = blockIdx.x * blockDim.x + threadIdx.x;
    unsigned long long key = 0ull;
    float ex = 0.f;
    if (i < N_NODES) {
        float lg = g_logits[i];
        uint32_t k1a, k1b; threefry(0u, 42u, 0u, 0u, k1a, k1b);
        uint32_t bits = jax_bits32(k1a, k1b, (uint32_t)i);
        float z = lg + gumbel_from_bits(bits);
        key = (((unsigned long long)fford(z)) << 32) | (unsigned long long)(0xFFFFFFFFu - (unsigned)i);
        ex = expf(lg);
    }
    for (int d2 = 16; d2; d2 >>= 1) {
        unsigned long long ok = __shfl_xor_sync(0xffffffffu, key, d2); if (ok > key) key = ok;
        ex += __shfl_xor_sync(0xffffffffu, ex, d2);
    }
    __shared__ unsigned long long sk[8];
    __shared__ float sv[8];
    int lane = threadIdx.x & 31, w = threadIdx.x >> 5;
    if (lane == 0) { sk[w] = key; sv[w] = ex; }
    __syncthreads();
    if (threadIdx.x == 0) {
        float t = 0.f;
        for (int q = 0; q < 8; q++) { if (sk[q] > key) key = sk[q]; t += sv[q]; }
        atomicMax(&g_amax, key);
        atomicAdd(&g_sexp, t);
    }
}

// final: layer-3 GATv2 only at selected node + action sampling + output
__global__ void k_final(const float* __restrict__ We3, const float* __restrict__ att3,
                        const float* __restrict__ bias3, float* __restrict__ out) {
    __shared__ float s3[4096];
    __shared__ int ssrc[4096];
    int t = threadIdx.x, lane = t & 31, w = t >> 5;
    int sel = (int)(0xFFFFFFFFu - (uint32_t)(g_amax & 0xFFFFFFFFull));
    int beg = g_off[sel], end = g_off[sel + 1];
    int cnt = end - beg;
    if (cnt > 4096) cnt = 4096;
    for (int p = w; p < cnt; p += 8) {
        int j = g_csrc[beg + p];
        float tt = g_h3[(size_t)sel * NACT + lane] + g_h3[(size_t)j * NACT + lane];
        const float* eap = &g_ea1[(size_t)(beg + p) * DE];
#pragma unroll
        for (int k = 0; k < DE; k++) tt += eap[k] * We3[k * NACT + lane];
        tt = lrelu(tt);
        float s = tt * att3[lane];
        for (int d2 = 16; d2; d2 >>= 1) s += __shfl_xor_sync(0xffffffffu, s, d2);
        if (lane == 0) { s3[p] = s; ssrc[p] = j; }
    }
    __syncthreads();
    if (w == 0) {
        float m = -INFINITY;
        for (int p = lane; p < cnt; p += 32) m = fmaxf(m, s3[p]);
        for (int d2 = 16; d2; d2 >>= 1) m = fmaxf(m, __shfl_xor_sync(0xffffffffu, m, d2));
        float den = 0;
        for (int p = lane; p < cnt; p += 32) den += expf(s3[p] - m);
        for (int d2 = 16; d2; d2 >>= 1) den += __shfl_xor_sync(0xffffffffu, den, d2);
        float acc = 0;
        for (int p = 0; p < cnt; p++) {
            float ex = expf(s3[p] - m);
            acc += ex * g_h3[(size_t)ssrc[p] * NACT + lane];
        }
        float logit = acc / (den + EPS_) + bias3[lane];
        uint32_t k2a, k2b; threefry(0u, 42u, 0u, 1u, k2a, k2b);
        uint32_t bits = jax_bits32(k2a, k2b, (uint32_t)lane);
        float z = logit + gumbel_from_bits(bits);
        float zb = z; int ib = lane;
        for (int d2 = 16; d2; d2 >>= 1) {
            float zo = __shfl_xor_sync(0xffffffffu, zb, d2);
            int io = __shfl_xor_sync(0xffffffffu, ib, d2);
            if (zo > zb || (zo == zb && io < ib)) { zb = zo; ib = io; }
        }
        int asel = ib;
        float lm = logit;
        for (int d2 = 16; d2; d2 >>= 1) lm = fmaxf(lm, __shfl_xor_sync(0xffffffffu, lm, d2));
        float se = expf(logit - lm);
        for (int d2 = 16; d2; d2 >>= 1) se += __shfl_xor_sync(0xffffffffu, se, d2);
        float logit_sel = __shfl_sync(0xffffffffu, logit, asel);
        if (lane == 0) {
            float alp = logit_sel - lm - logf(se);
            float nlp = g_logits[sel] - logf(g_sexp);
            out[0] = (float)sel;
            out[1] = (float)asel;
            out[2] = nlp + alp;
        }
    }
}

// ---------------- launch ----------------
extern "C" void kernel_launch(void* const* d_in, const int* in_sizes, int n_in,
                              void* d_out, int out_size) {
    const float* x     = (const float*)d_in[0];
    const int*   ei    = (const int*)  d_in[1];
    const float* ea    = (const float*)d_in[2];
    const float* Wl1   = (const float*)d_in[3];
    const float* bl1   = (const float*)d_in[4];
    const float* We1   = (const float*)d_in[5];
    const float* att1  = (const float*)d_in[6];
    const float* bias1 = (const float*)d_in[7];
    const float* Wl2   = (const float*)d_in[8];
    const float* bl2   = (const float*)d_in[9];
    const float* We2   = (const float*)d_in[10];
    const float* att2  = (const float*)d_in[11];
    const float* bias2 = (const float*)d_in[12];
    const float* Wl3   = (const float*)d_in[13];
    const float* bl3   = (const float*)d_in[14];
    const float* We3   = (const float*)d_in[15];
    const float* att3  = (const float*)d_in[16];
    const float* bias3 = (const float*)d_in[17];
    const int* src = ei;
    const int* dst = ei + N_EDGES;
    float* out = (float*)d_out;

    int ebl = (N_EDGES + 255) / 256;
    int nbl = (N_NODES + 255) / 256;
    int rowbl4 = (N_NODES + 3) / 4;                      // warp per row, 4 warps/block
    int rowbl8 = (N_NODES + 7) / 8;                      // warp per row, 8 warps/block
    int h1bl = ((N_NODES / 8) * 32 + 255) / 256;         // warp per 8 rows

    k_init<<<nbl, 256>>>();
    k_h1<<<h1bl, 256>>>(x, Wl1, bl1);
    k_count<<<ebl, 256>>>(dst);
    k_scanA<<<NB_SCAN, 1024>>>();
    k_scanB<<<1, 64>>>();
    k_scanC<<<NB_SCAN, 1024>>>();
    k_scatter<<<ebl, 256>>>(src, dst, ea, We2);
    k_l1<<<rowbl4, 128>>>(We1, att1, bias1, Wl2, bl2, Wl3, bl3);
    k_l2<<<rowbl8, 256>>>(att2, bias2);
    k_sel<<<nbl, 256>>>();
    k_final<<<1, 256>>>(We3, att3, bias3, out);
}